// round 1
// baseline (speedup 1.0000x reference)
#include <cuda_runtime.h>

#define IH 400
#define IW 400
#define NPIX (IH*IW)
#define KS 11
#define PAD 5
#define CIN 3
#define F1 128
#define F2 64
#define F3 8
#define TILE 16
#define TW (TILE + KS - 1)   // 26

// 82 MB scratch for h1 activations (device global: allocation-free)
__device__ float g_h1[(size_t)NPIX * F1];

// ---------------------------------------------------------------------------
// Kernel 1: 11x11 conv, 3 -> 128 channels, + bias + leaky_relu(0.01)
// Block: 256 threads = 16x16 pixel tile. gridDim.z = 4 channel groups of 32.
// ---------------------------------------------------------------------------
__global__ void __launch_bounds__(256) conv_k(const float* __restrict__ x,
                                              const float* __restrict__ W1,
                                              const float* __restrict__ b1)
{
    extern __shared__ float smem[];
    float* sx = smem;            // 3*26*26 = 2028 floats (slot 2048 for alignment)
    float* sw = smem + 2048;     // 363*32 = 11616 floats

    const int tid = threadIdx.x;
    const int x0 = blockIdx.x * TILE - PAD;
    const int y0 = blockIdx.y * TILE - PAD;

    // load x halo tile (zero-padded)
    for (int i = tid; i < CIN * TW * TW; i += 256) {
        int c = i / (TW * TW);
        int rem = i - c * (TW * TW);
        int r = rem / TW, col = rem - r * TW;
        int gy = y0 + r, gx = x0 + col;
        float v = 0.f;
        if ((unsigned)gy < (unsigned)IH && (unsigned)gx < (unsigned)IW)
            v = x[(c * IH + gy) * IW + gx];
        sx[i] = v;
    }

    // load 32-channel slice of W1 [363,128]
    const int base = blockIdx.z * 32;
    for (int i = tid; i < 363 * 32; i += 256) {
        int f = i >> 5, ch = i & 31;
        sw[i] = W1[f * F1 + base + ch];
    }
    __syncthreads();

    const int tx = tid & 15, ty = tid >> 4;

    float acc[32];
#pragma unroll
    for (int q = 0; q < 32; q++) acc[q] = 0.f;

#pragma unroll 1
    for (int c = 0; c < CIN; c++) {
#pragma unroll 1
        for (int ki = 0; ki < KS; ki++) {
            const float* xrow = &sx[c * (TW * TW) + (ty + ki) * TW + tx];
            const float4* wbase =
                (const float4*)&sw[(c * (KS * KS) + ki * KS) << 5];
#pragma unroll
            for (int kj = 0; kj < KS; kj++) {
                float xv = xrow[kj];
                const float4* wv = wbase + kj * 8;
#pragma unroll
                for (int q = 0; q < 8; q++) {
                    float4 w = wv[q];
                    acc[4 * q + 0] += xv * w.x;
                    acc[4 * q + 1] += xv * w.y;
                    acc[4 * q + 2] += xv * w.z;
                    acc[4 * q + 3] += xv * w.w;
                }
            }
        }
    }

    // bias + leaky, store to scratch
    const int px = blockIdx.x * TILE + tx;
    const int py = blockIdx.y * TILE + ty;
    float4* dst = (float4*)&g_h1[((size_t)(py * IW + px)) * F1 + base];
    const float* bb = b1 + base;
#pragma unroll
    for (int q = 0; q < 8; q++) {
        float4 v;
        float t;
        t = acc[4 * q + 0] + bb[4 * q + 0]; v.x = t > 0.f ? t : 0.01f * t;
        t = acc[4 * q + 1] + bb[4 * q + 1]; v.y = t > 0.f ? t : 0.01f * t;
        t = acc[4 * q + 2] + bb[4 * q + 2]; v.z = t > 0.f ? t : 0.01f * t;
        t = acc[4 * q + 3] + bb[4 * q + 3]; v.w = t > 0.f ? t : 0.01f * t;
        dst[q] = v;
    }
}

// ---------------------------------------------------------------------------
// Kernel 2: per-pixel 128->64 (leaky) -> 8, L2 normalize.
// One pixel per thread; W2 rows broadcast from smem; h2 in registers.
// ---------------------------------------------------------------------------
__global__ void __launch_bounds__(128) mlp_k(const float* __restrict__ W2,
                                             const float* __restrict__ b2,
                                             const float* __restrict__ W3,
                                             const float* __restrict__ b3,
                                             float* __restrict__ out)
{
    __shared__ float sW2[F1 * F2];   // [k][c] row-major: 32 KB
    __shared__ float sW3[F2 * F3];   // [k][e]: 2 KB
    __shared__ float sb2[F2];
    __shared__ float sb3[F3];

    const int tid = threadIdx.x;
    for (int i = tid; i < F1 * F2; i += 128) sW2[i] = W2[i];
    for (int i = tid; i < F2 * F3; i += 128) sW3[i] = W3[i];
    if (tid < F2) sb2[tid] = b2[tid];
    if (tid < F3) sb3[tid] = b3[tid];
    __syncthreads();

    const int p = blockIdx.x * 128 + tid;   // grid sized exactly: no bounds check needed
    if (p >= NPIX) return;

    float acc[F2];
#pragma unroll
    for (int c = 0; c < F2; c++) acc[c] = sb2[c];

    const float4* hrow = (const float4*)(g_h1 + (size_t)p * F1);

#pragma unroll 2
    for (int k4 = 0; k4 < F1 / 4; k4++) {
        float4 hc = hrow[k4];
        float hv[4] = {hc.x, hc.y, hc.z, hc.w};
#pragma unroll
        for (int kk = 0; kk < 4; kk++) {
            float xv = hv[kk];
            const float4* wr = (const float4*)&sW2[(4 * k4 + kk) * F2];
#pragma unroll
            for (int q = 0; q < F2 / 4; q++) {
                float4 w = wr[q];
                acc[4 * q + 0] += xv * w.x;
                acc[4 * q + 1] += xv * w.y;
                acc[4 * q + 2] += xv * w.z;
                acc[4 * q + 3] += xv * w.w;
            }
        }
    }

    // leaky
#pragma unroll
    for (int c = 0; c < F2; c++) {
        float t = acc[c];
        acc[c] = t > 0.f ? t : 0.01f * t;
    }

    // h3 = h2 @ W3 + b3
    float v[F3];
#pragma unroll
    for (int e = 0; e < F3; e++) v[e] = sb3[e];
#pragma unroll 8
    for (int k = 0; k < F2; k++) {
        float hk = acc[k];
        const float4* wr = (const float4*)&sW3[k * F3];
        float4 w0 = wr[0], w1 = wr[1];
        v[0] += hk * w0.x; v[1] += hk * w0.y; v[2] += hk * w0.z; v[3] += hk * w0.w;
        v[4] += hk * w1.x; v[5] += hk * w1.y; v[6] += hk * w1.z; v[7] += hk * w1.w;
    }

    // L2 normalize
    float ss = 0.f;
#pragma unroll
    for (int e = 0; e < F3; e++) ss += v[e] * v[e];
    float n = fmaxf(sqrtf(ss), 1e-12f);
    float inv = 1.0f / n;

    float4* o = (float4*)(out + (size_t)p * F3);
    float4 o0, o1;
    o0.x = v[0] * inv; o0.y = v[1] * inv; o0.z = v[2] * inv; o0.w = v[3] * inv;
    o1.x = v[4] * inv; o1.y = v[5] * inv; o1.z = v[6] * inv; o1.w = v[7] * inv;
    o[0] = o0;
    o[1] = o1;
}

// ---------------------------------------------------------------------------
extern "C" void kernel_launch(void* const* d_in, const int* in_sizes, int n_in,
                              void* d_out, int out_size)
{
    const float* x  = (const float*)d_in[0];   // [1,3,400,400]
    const float* W1 = (const float*)d_in[1];   // [363,128]
    const float* b1 = (const float*)d_in[2];   // [128]
    const float* W2 = (const float*)d_in[3];   // [128,64]
    const float* b2 = (const float*)d_in[4];   // [64]
    const float* W3 = (const float*)d_in[5];   // [64,8]
    const float* b3 = (const float*)d_in[6];   // [8]
    float* out = (float*)d_out;                // [400,400,8]

    const int smem1 = (2048 + 363 * 32) * sizeof(float);  // 54656 B
    cudaFuncSetAttribute(conv_k, cudaFuncAttributeMaxDynamicSharedMemorySize, smem1);

    dim3 grid1(IW / TILE, IH / TILE, F1 / 32);   // 25 x 25 x 4
    conv_k<<<grid1, 256, smem1>>>(x, W1, b1);

    dim3 grid2((NPIX + 127) / 128);              // 1250
    mlp_k<<<grid2, 128>>>(W2, b2, W3, b3, out);
}